// round 15
// baseline (speedup 1.0000x reference)
#include <cuda_runtime.h>
#include <math.h>

#define B_ 4
#define C_ 32
#define L_ 256
#define M_ 256
#define F_ 8
#define N_ 64
#define CL_ (L_ * M_)      // c-stride in x (elements)
#define HC_ 16             // c's per warp-group

typedef unsigned long long u64;

__device__ __forceinline__ u64 ffma2(u64 a, u64 b, u64 c) {
    u64 d;
    asm("fma.rn.f32x2 %0, %1, %2, %3;" : "=l"(d) : "l"(a), "l"(b), "l"(c));
    return d;
}
__device__ __forceinline__ u64 add2(u64 a, u64 b) {
    u64 d;
    asm("add.rn.f32x2 %0, %1, %2;" : "=l"(d) : "l"(a), "l"(b));
    return d;
}
__device__ __forceinline__ void upk(u64 v, float& x, float& y) {
    asm("mov.b64 {%0, %1}, %2;" : "=f"(x), "=f"(y) : "l"(v));
}
__device__ __forceinline__ u64 neg2(u64 v) {
    u64 d;
    asm("{\n\t"
        ".reg .b32 lo, hi;\n\t"
        "mov.b64 {lo, hi}, %1;\n\t"
        "xor.b32 lo, lo, 0x80000000;\n\t"
        "xor.b32 hi, hi, 0x80000000;\n\t"
        "mov.b64 %0, {lo, hi};\n\t"
        "}" : "=l"(d) : "l"(v));
    return d;
}

__global__ __launch_bounds__(256, 3) void sphere_conv_kernel(
    const float* __restrict__ xr, const float* __restrict__ xi,
    const float* __restrict__ wr, const float* __restrict__ wi,
    float* __restrict__ out)
{
    // weights {wr,wr,wi,wi} per (f,c): 4 KB ; reduction buffer: 16 KB
    __shared__ float4 w4s[C_ * F_];
    __shared__ u64    red[128][HC_];     // B-group partials: [m-pair][pr0..7,pi0..7]

    const int tid = threadIdx.x;
    const int ga  = tid >> 7;            // 0: c=0..15 (+epilogue), 1: c=16..31
    const int mt  = tid & 127;           // m-pair index; m = 2*mt, 2*mt+1
    const int bl  = blockIdx.x;          // b*L + l
    const int b   = bl >> 8;             // L_ == 256
    const int l   = bl & (L_ - 1);

    // ---- interpolated weights (all 256 (f,c) pairs, split across 256 thr) ----
    const float t = (float)(l * (N_ - 1)) * (1.0f / (float)(L_ - 1));
    int lo = (int)t;
    if (lo > N_ - 2) lo = N_ - 2;
    const float frac = t - (float)lo;
    const float om   = 1.0f - frac;
    {
        const int i = tid;               // 256 threads, 256 pairs: one each
        const int f = i & (F_ - 1);
        const int c = i >> 3;
        const int wix = (f * C_ + c) * N_ + lo;      // w layout (F,C,N,1)
        const float wrv = wr[wix] * om + wr[wix + 1] * frac;
        const float wiv = wi[wix] * om + wi[wix + 1] * frac;
        w4s[c * F_ + f] = make_float4(wrv, wrv, wiv, wiv);
    }
    __syncthreads();

    const unsigned int sw =
        (unsigned int)__cvta_generic_to_shared(w4s) +
        (unsigned)(ga * (HC_ * F_ * 16));

    u64 pr[F_], pi[F_];
#pragma unroll
    for (int f = 0; f < F_; ++f) { pr[f] = 0ull; pi[f] = 0ull; }

    // this group's c-range starts at ga*HC_
    const int base = b * (C_ * CL_) + (ga * HC_) * CL_ + l * M_ + 2 * mt;
    const float* xrp = xr + base;
    const float* xip = xi + base;

    // rolling double-buffered c-PAIRS over 16 c's (8 pairs)
    u64 buf[2][2][2];
#pragma unroll
    for (int j = 0; j < 2; ++j) {
        buf[0][j][0] = *(const u64*)(xrp + j * CL_);
        buf[0][j][1] = *(const u64*)(xip + j * CL_);
    }
    unsigned int soff = sw;
#pragma unroll
    for (int cp = 0; cp < 8; ++cp) {
        const int cur = cp & 1, nxt = cur ^ 1;
        if (cp < 7) {
#pragma unroll
            for (int j = 0; j < 2; ++j) {
                const int c = (cp + 1) * 2 + j;
                buf[nxt][j][0] = *(const u64*)(xrp + c * CL_);
                buf[nxt][j][1] = *(const u64*)(xip + c * CL_);
            }
        }
#pragma unroll
        for (int j = 0; j < 2; ++j) {
            const u64 x_r = buf[cur][j][0];
            const u64 x_i = buf[cur][j][1];
            const u64 nxi = neg2(x_i);
#pragma unroll
            for (int f = 0; f < F_; ++f) {
                u64 wrr, wii;
                asm("ld.shared.v2.u64 {%0, %1}, [%2];"
                    : "=l"(wrr), "=l"(wii)
                    : "r"(soff + (unsigned)(f * 16)));
                pr[f] = ffma2(wrr, x_r, pr[f]);   // + wr*xr
                pr[f] = ffma2(wii, nxi, pr[f]);   // - wi*xi
                pi[f] = ffma2(wii, x_r, pi[f]);   // + wi*xr
                pi[f] = ffma2(wrr, x_i, pi[f]);   // + wr*xi
            }
            soff += F_ * 16;             // next c
        }
    }

    // ---- cross-group reduction: B stores, A adds ----
    if (ga == 1) {
#pragma unroll
        for (int f = 0; f < F_; ++f) {
            red[mt][f]       = pr[f];
            red[mt][F_ + f]  = pi[f];
        }
    }
    __syncthreads();
    if (ga == 0) {
#pragma unroll
        for (int f = 0; f < F_; ++f) {
            pr[f] = add2(pr[f], red[mt][f]);
            pi[f] = add2(pi[f], red[mt][F_ + f]);
        }

        // ---- epilogue: scale = sqrt(1+l)/C, relu on real only ----
        const float s  = sqrtf(1.0f + (float)l) * (1.0f / (float)C_);
        float2* outp   = (float2*)out;
        const int ob   = (b * F_ * L_ + l) * M_ + 2 * mt;
#pragma unroll
        for (int f = 0; f < F_; ++f) {
            float r0, r1, i0, i1;
            upk(pr[f], r0, r1);
            upk(pi[f], i0, i1);
            const int idx = ob + f * (L_ * M_);
            outp[idx >> 1] = make_float2(fmaxf(r0 * s, 0.0f), fmaxf(r1 * s, 0.0f));
            outp[(idx + B_ * F_ * L_ * M_) >> 1] = make_float2(i0 * s, i1 * s);
        }
    }
}

extern "C" void kernel_launch(void* const* d_in, const int* in_sizes, int n_in,
                              void* d_out, int out_size) {
    (void)in_sizes; (void)n_in; (void)out_size;
    sphere_conv_kernel<<<B_ * L_, 256>>>(
        (const float*)d_in[0], (const float*)d_in[1],
        (const float*)d_in[2], (const float*)d_in[3],
        (float*)d_out);
}